// round 9
// baseline (speedup 1.0000x reference)
#include <cuda_runtime.h>
#include <math.h>

#define MAXN 50048
#define MAXE 800000
#define KIN 128
#define HID 64
#define NH 8
#define C2 40
#define NEG 0.2f
#define SXCH 36   // chunk row stride in floats (16B-aligned, conflict-free)

// ---------------- scratch (fp32 everywhere) ----------------
__device__ float g_h1[MAXN * HID];
__device__ float g_alS1[MAXN * NH];
__device__ float g_alD1[MAXN * NH];
__device__ float g_hact[MAXN * HID];
__device__ float g_h2[MAXN * C2];
__device__ float g_alS2[MAXN];
__device__ float g_alD2[MAXN];
// CSR
__device__ int g_cnt[MAXN];             // zero at entry (zero-init; scanC re-zeroes)
__device__ int g_incl[MAXN];
__device__ int g_rowstart[MAXN + 1];
__device__ int g_wcur[MAXN];
__device__ int g_eidx[MAXE];
__device__ int g_bsum[64];

__device__ __forceinline__ unsigned smem_u32(const void* p) {
    unsigned a;
    asm("{ .reg .u64 t; cvta.to.shared.u64 t, %1; cvt.u32.u64 %0, t; }" : "=r"(a) : "l"(p));
    return a;
}

// ---------------- CSR build ----------------
__global__ void count_k(const int* __restrict__ ei, int E) {
    int i = blockIdx.x * blockDim.x + threadIdx.x;
    if (i < E) atomicAdd(&g_cnt[ei[E + i]], 1);
}

__global__ void scanA_k(int n) {
    __shared__ int s[1024];
    int i = blockIdx.x * 1024 + threadIdx.x;
    s[threadIdx.x] = (i < n) ? g_cnt[i] : 0;
    __syncthreads();
#pragma unroll
    for (int o = 1; o < 1024; o <<= 1) {
        int t = 0;
        if (threadIdx.x >= o) t = s[threadIdx.x - o];
        __syncthreads();
        if (threadIdx.x >= o) s[threadIdx.x] += t;
        __syncthreads();
    }
    if (i < n) g_incl[i] = s[threadIdx.x];
    if (threadIdx.x == 1023) g_bsum[blockIdx.x] = s[1023];
}

__global__ void scanC_k(int n, int E, int nb) {
    __shared__ int sb[64];
    int t = threadIdx.x;
    if (t < 64) sb[t] = (t < nb) ? g_bsum[t] : 0;
    __syncthreads();
    int i = blockIdx.x * blockDim.x + t;
    if (i == 0) g_rowstart[n] = E;
    if (i < n) {
        int b = i >> 10;
        int base = 0;
        for (int k = 0; k < b; k++) base += sb[k];
        int start = g_incl[i] - g_cnt[i] + base;
        g_rowstart[i] = start;
        g_wcur[i] = start;
        g_cnt[i] = 0;
    }
}

__global__ void scatter_k(const int* __restrict__ ei, int E) {
    int i = blockIdx.x * blockDim.x + threadIdx.x;
    if (i < E) {
        int dst = ei[E + i];
        int pos = atomicAdd(&g_wcur[dst], 1);
        g_eidx[pos] = ei[i];
    }
}

// ---------------- layer 1 GEMM: cp.async double-buffered, k-vectorized LDS ----------------
__global__ __launch_bounds__(256) void gemm1_k(
        const float* __restrict__ x, const float* __restrict__ topo,
        const float* __restrict__ W1,
        const float* __restrict__ a_src, const float* __restrict__ a_dst, int n) {
    extern __shared__ float smem[];
    float* sW  = smem;                        // 8192 floats
    float* sX0 = smem + 8192;                 // 64*36
    float* sX1 = sX0 + 64 * SXCH;             // 64*36
    float* sLS = sX1 + 64 * SXCH;             // 512
    float* sLD = sLS + 512;                   // 512
    int t = threadIdx.x;
    int row0 = blockIdx.x * 64;

    {
        const float4* W14 = reinterpret_cast<const float4*>(W1);
        float4* sW4w = reinterpret_cast<float4*>(sW);
        for (int i = t; i < KIN * HID / 4; i += 256) sW4w[i] = W14[i];
    }
    for (int i = t; i < 512; i += 256) { sLS[i] = 0.f; sLD[i] = 0.f; }

    int rA = t >> 3, qA = t & 7;
    int rB = (t + 256) >> 3, qB = (t + 256) & 7;
    int gsA = (row0 + rA < n) ? row0 + rA : 0;
    int gsB = (row0 + rB < n) ? row0 + rB : 0;
    const float4* xA = reinterpret_cast<const float4*>(x + gsA * 120);
    const float4* tA = reinterpret_cast<const float4*>(topo + gsA * 8);
    const float4* xB = reinterpret_cast<const float4*>(x + gsB * 120);
    const float4* tB = reinterpret_cast<const float4*>(topo + gsB * 8);
    unsigned dA0 = smem_u32(sX0 + rA * SXCH + qA * 4);
    unsigned dB0 = smem_u32(sX0 + rB * SXCH + qB * 4);
    unsigned dA1 = smem_u32(sX1 + rA * SXCH + qA * 4);
    unsigned dB1 = smem_u32(sX1 + rB * SXCH + qB * 4);

#define ISSUE_CHUNK(kc, dA, dB)                                              \
    {                                                                        \
        const float4* sA = ((kc) < 3) ? (xA + (kc) * 8 + qA)                 \
                          : ((qA < 6) ? (xA + 24 + qA) : (tA + (qA - 6)));   \
        const float4* sB = ((kc) < 3) ? (xB + (kc) * 8 + qB)                 \
                          : ((qB < 6) ? (xB + 24 + qB) : (tB + (qB - 6)));   \
        asm volatile("cp.async.cg.shared.global [%0], [%1], 16;\n"           \
                     :: "r"(dA), "l"(sA) : "memory");                        \
        asm volatile("cp.async.cg.shared.global [%0], [%1], 16;\n"           \
                     :: "r"(dB), "l"(sB) : "memory");                        \
        asm volatile("cp.async.commit_group;\n" ::: "memory");               \
    }

    ISSUE_CHUNK(0, dA0, dB0)

    int rg = t >> 4;
    int cg = t & 15;
    float acc[4][4];
#pragma unroll
    for (int r = 0; r < 4; r++)
#pragma unroll
        for (int c = 0; c < 4; c++) acc[r][c] = 0.f;

    const float4* sW4 = reinterpret_cast<const float4*>(sW);
#pragma unroll
    for (int kc = 0; kc < 4; kc++) {
        if (kc == 0)      ISSUE_CHUNK(1, dA1, dB1)
        else if (kc == 1) ISSUE_CHUNK(2, dA0, dB0)
        else if (kc == 2) ISSUE_CHUNK(3, dA1, dB1)
        if (kc < 3) asm volatile("cp.async.wait_group 1;\n" ::: "memory");
        else        asm volatile("cp.async.wait_group 0;\n" ::: "memory");
        __syncthreads();
        const float* bx = (kc & 1) ? sX1 : sX0;
#pragma unroll
        for (int kq = 0; kq < 8; kq++) {          // 8 x 4-k groups = 32 k
            float4 xr[4];
#pragma unroll
            for (int r = 0; r < 4; r++)
                xr[r] = *reinterpret_cast<const float4*>(&bx[(rg * 4 + r) * SXCH + kq * 4]);
            float xk[4][4];
#pragma unroll
            for (int r = 0; r < 4; r++) {
                xk[r][0] = xr[r].x; xk[r][1] = xr[r].y;
                xk[r][2] = xr[r].z; xk[r][3] = xr[r].w;
            }
#pragma unroll
            for (int kk = 0; kk < 4; kk++) {
                float4 wv = sW4[(kc * 32 + kq * 4 + kk) * 16 + cg];
#pragma unroll
                for (int r = 0; r < 4; r++) {
                    acc[r][0] += xk[r][kk] * wv.x;
                    acc[r][1] += xk[r][kk] * wv.y;
                    acc[r][2] += xk[r][kk] * wv.z;
                    acc[r][3] += xk[r][kk] * wv.w;
                }
            }
        }
        __syncthreads();
    }
#undef ISSUE_CHUNK

    int hd = cg >> 1;
    int off = (cg & 1) * 4;
    float4* g_h1_4 = reinterpret_cast<float4*>(g_h1);
#pragma unroll
    for (int r = 0; r < 4; r++) {
        int lr = rg * 4 + r;
        int gr = row0 + lr;
        if (gr < n) {
            float4 o;
            o.x = acc[r][0]; o.y = acc[r][1]; o.z = acc[r][2]; o.w = acc[r][3];
            g_h1_4[gr * 16 + cg] = o;
        }
        float ps = 0.f, pd = 0.f;
#pragma unroll
        for (int j = 0; j < 4; j++) {
            ps += acc[r][j] * a_src[hd * 8 + off + j];
            pd += acc[r][j] * a_dst[hd * 8 + off + j];
        }
        atomicAdd(&sLS[lr * 8 + hd], ps);
        atomicAdd(&sLD[lr * 8 + hd], pd);
    }
    __syncthreads();
    for (int i = t; i < 512; i += 256) {
        int lr = i >> 3, h = i & 7;
        int gr = row0 + lr;
        if (gr < n) {
            g_alS1[gr * 8 + h] = sLS[i];
            g_alD1[gr * 8 + h] = sLD[i];
        }
    }
}

// ---------------- layer 1 aggregation: warp/node, 4 edges/iter, 1-deep prefetch ----------------
__global__ __launch_bounds__(256) void agg1_k(const float* __restrict__ b1, int n) {
    int w = (blockIdx.x * blockDim.x + threadIdx.x) >> 5;
    if (w >= n) return;
    int l = threadIdx.x & 31;
    int h0 = l >> 3;
    int hh = l & 7;
    float alDh = g_alD1[w * 8 + hh];
    int beg = g_rowstart[w], end = g_rowstart[w + 1];
    float acc0 = 0.f, acc1 = 0.f, qsum = 0.f;
    // self loop
    {
        float a = g_alS1[w * 8 + hh] + alDh;
        a = a > 0.f ? a : NEG * a;
        float q = __expf(a);
        if (l < 8) qsum += q;
        float p0 = __shfl_sync(0xFFFFFFFFu, q, h0);
        float p1 = __shfl_sync(0xFFFFFFFFu, q, h0 + 4);
        acc0 += p0 * g_h1[w * HID + l];
        acc1 += p1 * g_h1[w * HID + 32 + l];
    }
    // pipeline prologue: batch at j=beg
    int srcC = 0; float aC = 0.f; bool vC = false;
    if (beg < end) {
        int jj = beg + h0;
        vC = jj < end;
        srcC = g_eidx[vC ? jj : beg];
        aC = g_alS1[srcC * 8 + hh];
    }
    for (int j = beg; j < end; j += 4) {
        // prefetch next batch metadata (overlaps with this batch's gathers)
        int srcN = 0; float aN = 0.f; bool vN = false;
        int jn = j + 4;
        if (jn < end) {
            int jj = jn + h0;
            vN = jj < end;
            srcN = g_eidx[vN ? jj : jn];
            aN = g_alS1[srcN * 8 + hh];
        }
        float a = aC + alDh;
        a = a > 0.f ? a : NEG * a;
        float q = vC ? __expf(a) : 0.f;
        qsum += q;
        int nleft = end - j;
#pragma unroll
        for (int e2 = 0; e2 < 4; e2++) {
            if (e2 >= nleft) break;
            float p0 = __shfl_sync(0xFFFFFFFFu, q, e2 * 8 + h0);
            float p1 = __shfl_sync(0xFFFFFFFFu, q, e2 * 8 + h0 + 4);
            int sv = __shfl_sync(0xFFFFFFFFu, srcC, e2 * 8);
            acc0 += p0 * g_h1[sv * HID + l];
            acc1 += p1 * g_h1[sv * HID + 32 + l];
        }
        srcC = srcN; aC = aN; vC = vN;
    }
    qsum += __shfl_xor_sync(0xFFFFFFFFu, qsum, 8);
    qsum += __shfl_xor_sync(0xFFFFFFFFu, qsum, 16);
    float s0 = __shfl_sync(0xFFFFFFFFu, qsum, h0);
    float s1 = __shfl_sync(0xFFFFFFFFu, qsum, h0 + 4);
    float v0 = acc0 / s0 + b1[l];
    float v1 = acc1 / s1 + b1[32 + l];
    g_hact[w * HID + l]      = v0 > 0.f ? v0 : expm1f(v0);
    g_hact[w * HID + 32 + l] = v1 > 0.f ? v1 : expm1f(v1);
}

// ---------------- layer 2 GEMM (R8) ----------------
__global__ __launch_bounds__(160) void gemm2_k(
        const float* __restrict__ W2,
        const float* __restrict__ a_src2, const float* __restrict__ a_dst2, int n) {
    __shared__ float sW[HID * C2];
    __shared__ float sX[64 * HID];
    __shared__ float sLS[64];
    __shared__ float sLD[64];
    int t = threadIdx.x;
    int row0 = blockIdx.x * 64;
    for (int i = t; i < HID * C2; i += 160) sW[i] = W2[i];
    for (int i = t; i < 64 * HID; i += 160) {
        int r = i >> 6, c = i & 63;
        int gr = row0 + r;
        sX[i] = (gr < n) ? g_hact[gr * HID + c] : 0.f;
    }
    if (t < 64) { sLS[t] = 0.f; sLD[t] = 0.f; }
    __syncthreads();

    int cg = t % 10;
    int rg = t / 10;
    float acc[4][4];
#pragma unroll
    for (int r = 0; r < 4; r++)
#pragma unroll
        for (int c = 0; c < 4; c++) acc[r][c] = 0.f;

    const float4* sW4 = reinterpret_cast<const float4*>(sW);
#pragma unroll 4
    for (int k = 0; k < HID; k++) {
        float4 wv = sW4[k * 10 + cg];
        float xv0 = sX[(rg * 4 + 0) * HID + k];
        float xv1 = sX[(rg * 4 + 1) * HID + k];
        float xv2 = sX[(rg * 4 + 2) * HID + k];
        float xv3 = sX[(rg * 4 + 3) * HID + k];
#define STEP(r, xv) \
        acc[r][0] += xv * wv.x; acc[r][1] += xv * wv.y; \
        acc[r][2] += xv * wv.z; acc[r][3] += xv * wv.w;
        STEP(0, xv0) STEP(1, xv1) STEP(2, xv2) STEP(3, xv3)
#undef STEP
    }

#pragma unroll
    for (int r = 0; r < 4; r++) {
        int lr = rg * 4 + r;
        int gr = row0 + lr;
        float ps = 0.f, pd = 0.f;
#pragma unroll
        for (int j = 0; j < 4; j++) {
            int c = cg * 4 + j;
            if (gr < n) g_h2[gr * C2 + c] = acc[r][j];
            ps += acc[r][j] * a_src2[c];
            pd += acc[r][j] * a_dst2[c];
        }
        atomicAdd(&sLS[lr], ps);
        atomicAdd(&sLD[lr], pd);
    }
    __syncthreads();
    if (t < 64) {
        int gr = row0 + t;
        if (gr < n) { g_alS2[gr] = sLS[t]; g_alD2[gr] = sLD[t]; }
    }
}

// ---------------- layer 2 aggregation + log_softmax: 32 edges/iter, 1-deep prefetch ----------------
__global__ __launch_bounds__(256) void agg2_k(const float* __restrict__ b2,
                                              float* __restrict__ out, int n) {
    int w = (blockIdx.x * blockDim.x + threadIdx.x) >> 5;
    if (w >= n) return;
    int l = threadIdx.x & 31;
    float alDv = g_alD2[w];
    int beg = g_rowstart[w], end = g_rowstart[w + 1];
    float acc0 = 0.f, acc1 = 0.f, ssum = 0.f;
    // self loop
    {
        float e = g_alS2[w] + alDv;
        e = e > 0.f ? e : NEG * e;
        float p = __expf(e);
        if (l == 0) ssum += p;
        acc0 += p * g_h2[w * C2 + l];
        if (l < 8) acc1 += p * g_h2[w * C2 + 32 + l];
    }
    // pipeline prologue
    int srcC = 0; float aC = 0.f; bool vC = false;
    if (beg < end) {
        int jj = beg + l;
        vC = jj < end;
        srcC = g_eidx[vC ? jj : beg];
        aC = g_alS2[srcC];
    }
    for (int j = beg; j < end; j += 32) {
        int srcN = 0; float aN = 0.f; bool vN = false;
        int jn = j + 32;
        if (jn < end) {
            int jj = jn + l;
            vN = jj < end;
            srcN = g_eidx[vN ? jj : jn];
            aN = g_alS2[srcN];
        }
        float e = aC + alDv;
        e = e > 0.f ? e : NEG * e;
        float q = vC ? __expf(e) : 0.f;
        ssum += q;
        int m = min(32, end - j);
        for (int e2 = 0; e2 < m; e2++) {
            float pp = __shfl_sync(0xFFFFFFFFu, q, e2);
            int sv = __shfl_sync(0xFFFFFFFFu, srcC, e2);
            acc0 += pp * g_h2[sv * C2 + l];
            if (l < 8) acc1 += pp * g_h2[sv * C2 + 32 + l];
        }
        srcC = srcN; aC = aN; vC = vN;
    }
#pragma unroll
    for (int o = 16; o; o >>= 1) ssum += __shfl_xor_sync(0xFFFFFFFFu, ssum, o);
    float inv = 1.f / ssum;
    float v0 = acc0 * inv + b2[l];
    float v1 = (l < 8) ? (acc1 * inv + b2[32 + l]) : -3.0e38f;
    float m = fmaxf(v0, v1);
#pragma unroll
    for (int o = 16; o; o >>= 1) m = fmaxf(m, __shfl_xor_sync(0xFFFFFFFFu, m, o));
    float se = __expf(v0 - m) + ((l < 8) ? __expf(v1 - m) : 0.f);
#pragma unroll
    for (int o = 16; o; o >>= 1) se += __shfl_xor_sync(0xFFFFFFFFu, se, o);
    float lse = logf(se) + m;
    out[w * C2 + l] = v0 - lse;
    if (l < 8) out[w * C2 + 32 + l] = v1 - lse;
}

// ---------------- launcher ----------------
extern "C" void kernel_launch(void* const* d_in, const int* in_sizes, int n_in,
                              void* d_out, int out_size) {
    const float* x    = (const float*)d_in[0];
    const float* topo = (const float*)d_in[1];
    const int*   ei   = (const int*)d_in[2];
    const float* W1   = (const float*)d_in[3];
    const float* a_s1 = (const float*)d_in[4];
    const float* a_d1 = (const float*)d_in[5];
    const float* b1   = (const float*)d_in[6];
    const float* W2   = (const float*)d_in[7];
    const float* a_s2 = (const float*)d_in[8];
    const float* a_d2 = (const float*)d_in[9];
    const float* b2   = (const float*)d_in[10];
    float* out = (float*)d_out;

    int n = in_sizes[0] / 120;
    int E = in_sizes[2] / 2;
    int nb = (n + 1023) >> 10;

    const int GEMM1_SMEM = (8192 + 2 * 64 * SXCH + 1024) * 4;   // 55296 B
    cudaFuncSetAttribute(gemm1_k, cudaFuncAttributeMaxDynamicSharedMemorySize, GEMM1_SMEM);

    // gemm1 placed 4th (ncu capture slot)
    count_k<<<(E + 255) / 256, 256>>>(ei, E);
    scanA_k<<<nb, 1024>>>(n);
    scanC_k<<<(n + 255) / 256, 256>>>(n, E, nb);
    gemm1_k<<<(n + 63) / 64, 256, GEMM1_SMEM>>>(x, topo, W1, a_s1, a_d1, n);
    scatter_k<<<(E + 255) / 256, 256>>>(ei, E);
    agg1_k<<<(n * 32 + 255) / 256, 256>>>(b1, n);
    gemm2_k<<<(n + 63) / 64, 160>>>(W2, a_s2, a_d2, n);
    agg2_k<<<(n * 32 + 255) / 256, 256>>>(b2, out, n);
}

// round 10
// speedup vs baseline: 1.0148x; 1.0148x over previous
#include <cuda_runtime.h>
#include <math.h>

#define MAXN 50048
#define MAXE 800000
#define KIN 128
#define HID 64
#define NH 8
#define C2 40
#define NEG 0.2f
#define SXCH 36   // chunk row stride in floats (16B-aligned, conflict-free)
#define AUXB 128  // aux (count/scatter) blocks appended to each gemm1 launch

// ---------------- scratch (fp32 everywhere) ----------------
__device__ float g_h1[MAXN * HID];
__device__ float g_alS1[MAXN * NH];
__device__ float g_alD1[MAXN * NH];
__device__ float g_hact[MAXN * HID];
__device__ float g_h2[MAXN * C2];
__device__ float g_alS2[MAXN];
__device__ float g_alD2[MAXN];
// CSR
__device__ int g_cnt[MAXN];             // zero at entry (zero-init; scanC re-zeroes)
__device__ int g_incl[MAXN];
__device__ int g_rowstart[MAXN + 1];
__device__ int g_wcur[MAXN];
__device__ int g_eidx[MAXE];
__device__ int g_bsum[64];

__device__ __forceinline__ unsigned smem_u32(const void* p) {
    unsigned a;
    asm("{ .reg .u64 t; cvta.to.shared.u64 t, %1; cvt.u32.u64 %0, t; }" : "=r"(a) : "l"(p));
    return a;
}

// ---------------- scans ----------------
__global__ void scanA_k(int n) {
    __shared__ int s[1024];
    int i = blockIdx.x * 1024 + threadIdx.x;
    s[threadIdx.x] = (i < n) ? g_cnt[i] : 0;
    __syncthreads();
#pragma unroll
    for (int o = 1; o < 1024; o <<= 1) {
        int t = 0;
        if (threadIdx.x >= o) t = s[threadIdx.x - o];
        __syncthreads();
        if (threadIdx.x >= o) s[threadIdx.x] += t;
        __syncthreads();
    }
    if (i < n) g_incl[i] = s[threadIdx.x];
    if (threadIdx.x == 1023) g_bsum[blockIdx.x] = s[1023];
}

__global__ void scanC_k(int n, int E, int nb) {
    __shared__ int sb[64];
    int t = threadIdx.x;
    if (t < 64) sb[t] = (t < nb) ? g_bsum[t] : 0;
    __syncthreads();
    int i = blockIdx.x * blockDim.x + t;
    if (i == 0) g_rowstart[n] = E;
    if (i < n) {
        int b = i >> 10;
        int base = 0;
        for (int k = 0; k < b; k++) base += sb[k];
        int start = g_incl[i] - g_cnt[i] + base;
        g_rowstart[i] = start;
        g_wcur[i] = start;
        g_cnt[i] = 0;
    }
}

// ---------------- fused layer-1 GEMM (half) + aux CSR blocks ----------------
// Blocks [0, gblocks): gemm1 rows (rowbase+blk)*64..+63 (R8 cp.async pipeline).
// Blocks [gblocks, gblocks+AUXB): grid-stride aux. phase 0 = count, 1 = scatter.
__global__ __launch_bounds__(256) void g1aux_k(
        const float* __restrict__ x, const float* __restrict__ topo,
        const float* __restrict__ W1,
        const float* __restrict__ a_src, const float* __restrict__ a_dst,
        const int* __restrict__ ei,
        int n, int E, int gblocks, int rowbase, int phase) {
    if ((int)blockIdx.x >= gblocks) {
        int tid = ((int)blockIdx.x - gblocks) * 256 + threadIdx.x;
        int stride = AUXB * 256;
        if (phase == 0) {
            for (int i = tid; i < E; i += stride)
                atomicAdd(&g_cnt[ei[E + i]], 1);
        } else {
#pragma unroll 4
            for (int i = tid; i < E; i += stride) {
                int dst = ei[E + i];
                int pos = atomicAdd(&g_wcur[dst], 1);
                g_eidx[pos] = ei[i];
            }
        }
        return;
    }

    extern __shared__ float smem[];
    float* sW  = smem;                        // 8192 floats
    float* sX0 = smem + 8192;                 // 64*36
    float* sX1 = sX0 + 64 * SXCH;             // 64*36
    float* sLS = sX1 + 64 * SXCH;             // 512
    float* sLD = sLS + 512;                   // 512
    int t = threadIdx.x;
    int row0 = (rowbase + (int)blockIdx.x) * 64;

    {
        const float4* W14 = reinterpret_cast<const float4*>(W1);
        float4* sW4w = reinterpret_cast<float4*>(sW);
        for (int i = t; i < KIN * HID / 4; i += 256) sW4w[i] = W14[i];
    }
    for (int i = t; i < 512; i += 256) { sLS[i] = 0.f; sLD[i] = 0.f; }

    int rA = t >> 3, qA = t & 7;
    int rB = (t + 256) >> 3, qB = (t + 256) & 7;
    int gsA = (row0 + rA < n) ? row0 + rA : 0;
    int gsB = (row0 + rB < n) ? row0 + rB : 0;
    const float4* xA = reinterpret_cast<const float4*>(x + gsA * 120);
    const float4* tA = reinterpret_cast<const float4*>(topo + gsA * 8);
    const float4* xB = reinterpret_cast<const float4*>(x + gsB * 120);
    const float4* tB = reinterpret_cast<const float4*>(topo + gsB * 8);
    unsigned dA0 = smem_u32(sX0 + rA * SXCH + qA * 4);
    unsigned dB0 = smem_u32(sX0 + rB * SXCH + qB * 4);
    unsigned dA1 = smem_u32(sX1 + rA * SXCH + qA * 4);
    unsigned dB1 = smem_u32(sX1 + rB * SXCH + qB * 4);

#define ISSUE_CHUNK(kc, dA, dB)                                              \
    {                                                                        \
        const float4* sA = ((kc) < 3) ? (xA + (kc) * 8 + qA)                 \
                          : ((qA < 6) ? (xA + 24 + qA) : (tA + (qA - 6)));   \
        const float4* sB = ((kc) < 3) ? (xB + (kc) * 8 + qB)                 \
                          : ((qB < 6) ? (xB + 24 + qB) : (tB + (qB - 6)));   \
        asm volatile("cp.async.cg.shared.global [%0], [%1], 16;\n"           \
                     :: "r"(dA), "l"(sA) : "memory");                        \
        asm volatile("cp.async.cg.shared.global [%0], [%1], 16;\n"           \
                     :: "r"(dB), "l"(sB) : "memory");                        \
        asm volatile("cp.async.commit_group;\n" ::: "memory");               \
    }

    ISSUE_CHUNK(0, dA0, dB0)

    int rg = t >> 4;
    int cg = t & 15;
    float acc[4][4];
#pragma unroll
    for (int r = 0; r < 4; r++)
#pragma unroll
        for (int c = 0; c < 4; c++) acc[r][c] = 0.f;

    const float4* sW4 = reinterpret_cast<const float4*>(sW);
#pragma unroll
    for (int kc = 0; kc < 4; kc++) {
        if (kc == 0)      ISSUE_CHUNK(1, dA1, dB1)
        else if (kc == 1) ISSUE_CHUNK(2, dA0, dB0)
        else if (kc == 2) ISSUE_CHUNK(3, dA1, dB1)
        if (kc < 3) asm volatile("cp.async.wait_group 1;\n" ::: "memory");
        else        asm volatile("cp.async.wait_group 0;\n" ::: "memory");
        __syncthreads();
        const float* bx = (kc & 1) ? sX1 : sX0;
#pragma unroll 8
        for (int k = 0; k < 32; k++) {
            float4 wv = sW4[(kc * 32 + k) * 16 + cg];
            float xv0 = bx[(rg * 4 + 0) * SXCH + k];
            float xv1 = bx[(rg * 4 + 1) * SXCH + k];
            float xv2 = bx[(rg * 4 + 2) * SXCH + k];
            float xv3 = bx[(rg * 4 + 3) * SXCH + k];
#define STEP(r, xv) \
            acc[r][0] += xv * wv.x; acc[r][1] += xv * wv.y; \
            acc[r][2] += xv * wv.z; acc[r][3] += xv * wv.w;
            STEP(0, xv0) STEP(1, xv1) STEP(2, xv2) STEP(3, xv3)
#undef STEP
        }
        __syncthreads();
    }
#undef ISSUE_CHUNK

    int hd = cg >> 1;
    int off = (cg & 1) * 4;
    float4* g_h1_4 = reinterpret_cast<float4*>(g_h1);
#pragma unroll
    for (int r = 0; r < 4; r++) {
        int lr = rg * 4 + r;
        int gr = row0 + lr;
        if (gr < n) {
            float4 o;
            o.x = acc[r][0]; o.y = acc[r][1]; o.z = acc[r][2]; o.w = acc[r][3];
            g_h1_4[gr * 16 + cg] = o;
        }
        float ps = 0.f, pd = 0.f;
#pragma unroll
        for (int j = 0; j < 4; j++) {
            ps += acc[r][j] * a_src[hd * 8 + off + j];
            pd += acc[r][j] * a_dst[hd * 8 + off + j];
        }
        atomicAdd(&sLS[lr * 8 + hd], ps);
        atomicAdd(&sLD[lr * 8 + hd], pd);
    }
    __syncthreads();
    for (int i = t; i < 512; i += 256) {
        int lr = i >> 3, h = i & 7;
        int gr = row0 + lr;
        if (gr < n) {
            g_alS1[gr * 8 + h] = sLS[i];
            g_alD1[gr * 8 + h] = sLD[i];
        }
    }
}

// ---------------- layer 1 aggregation (R8, fp32) ----------------
__global__ __launch_bounds__(256) void agg1_k(const float* __restrict__ b1, int n) {
    int w = (blockIdx.x * blockDim.x + threadIdx.x) >> 5;
    if (w >= n) return;
    int l = threadIdx.x & 31;
    int h0 = l >> 3;
    int hh = l & 7;
    float alDh = g_alD1[w * 8 + hh];
    int beg = g_rowstart[w], end = g_rowstart[w + 1];
    float acc0 = 0.f, acc1 = 0.f, qsum = 0.f;
    {
        float a = g_alS1[w * 8 + hh] + alDh;
        a = a > 0.f ? a : NEG * a;
        float q = __expf(a);
        if (l < 8) qsum += q;
        float p0 = __shfl_sync(0xFFFFFFFFu, q, h0);
        float p1 = __shfl_sync(0xFFFFFFFFu, q, h0 + 4);
        acc0 += p0 * g_h1[w * HID + l];
        acc1 += p1 * g_h1[w * HID + 32 + l];
    }
    for (int j = beg; j < end; j += 4) {
        int jj = j + h0;
        bool valid = jj < end;
        int srcv = g_eidx[valid ? jj : j];
        float a = g_alS1[srcv * 8 + hh] + alDh;
        a = a > 0.f ? a : NEG * a;
        float q = valid ? __expf(a) : 0.f;
        qsum += q;
        int nleft = end - j;
#pragma unroll
        for (int e2 = 0; e2 < 4; e2++) {
            if (e2 >= nleft) break;
            float p0 = __shfl_sync(0xFFFFFFFFu, q, e2 * 8 + h0);
            float p1 = __shfl_sync(0xFFFFFFFFu, q, e2 * 8 + h0 + 4);
            int sv = __shfl_sync(0xFFFFFFFFu, srcv, e2 * 8);
            acc0 += p0 * g_h1[sv * HID + l];
            acc1 += p1 * g_h1[sv * HID + 32 + l];
        }
    }
    qsum += __shfl_xor_sync(0xFFFFFFFFu, qsum, 8);
    qsum += __shfl_xor_sync(0xFFFFFFFFu, qsum, 16);
    float s0 = __shfl_sync(0xFFFFFFFFu, qsum, h0);
    float s1 = __shfl_sync(0xFFFFFFFFu, qsum, h0 + 4);
    float v0 = acc0 / s0 + b1[l];
    float v1 = acc1 / s1 + b1[32 + l];
    g_hact[w * HID + l]      = v0 > 0.f ? v0 : expm1f(v0);
    g_hact[w * HID + 32 + l] = v1 > 0.f ? v1 : expm1f(v1);
}

// ---------------- layer 2 GEMM (R8) ----------------
__global__ __launch_bounds__(160) void gemm2_k(
        const float* __restrict__ W2,
        const float* __restrict__ a_src2, const float* __restrict__ a_dst2, int n) {
    __shared__ float sW[HID * C2];
    __shared__ float sX[64 * HID];
    __shared__ float sLS[64];
    __shared__ float sLD[64];
    int t = threadIdx.x;
    int row0 = blockIdx.x * 64;
    for (int i = t; i < HID * C2; i += 160) sW[i] = W2[i];
    for (int i = t; i < 64 * HID; i += 160) {
        int r = i >> 6, c = i & 63;
        int gr = row0 + r;
        sX[i] = (gr < n) ? g_hact[gr * HID + c] : 0.f;
    }
    if (t < 64) { sLS[t] = 0.f; sLD[t] = 0.f; }
    __syncthreads();

    int cg = t % 10;
    int rg = t / 10;
    float acc[4][4];
#pragma unroll
    for (int r = 0; r < 4; r++)
#pragma unroll
        for (int c = 0; c < 4; c++) acc[r][c] = 0.f;

    const float4* sW4 = reinterpret_cast<const float4*>(sW);
#pragma unroll 4
    for (int k = 0; k < HID; k++) {
        float4 wv = sW4[k * 10 + cg];
        float xv0 = sX[(rg * 4 + 0) * HID + k];
        float xv1 = sX[(rg * 4 + 1) * HID + k];
        float xv2 = sX[(rg * 4 + 2) * HID + k];
        float xv3 = sX[(rg * 4 + 3) * HID + k];
#define STEP(r, xv) \
        acc[r][0] += xv * wv.x; acc[r][1] += xv * wv.y; \
        acc[r][2] += xv * wv.z; acc[r][3] += xv * wv.w;
        STEP(0, xv0) STEP(1, xv1) STEP(2, xv2) STEP(3, xv3)
#undef STEP
    }

#pragma unroll
    for (int r = 0; r < 4; r++) {
        int lr = rg * 4 + r;
        int gr = row0 + lr;
        float ps = 0.f, pd = 0.f;
#pragma unroll
        for (int j = 0; j < 4; j++) {
            int c = cg * 4 + j;
            if (gr < n) g_h2[gr * C2 + c] = acc[r][j];
            ps += acc[r][j] * a_src2[c];
            pd += acc[r][j] * a_dst2[c];
        }
        atomicAdd(&sLS[lr], ps);
        atomicAdd(&sLD[lr], pd);
    }
    __syncthreads();
    if (t < 64) {
        int gr = row0 + t;
        if (gr < n) { g_alS2[gr] = sLS[t]; g_alD2[gr] = sLD[t]; }
    }
}

// ---------------- layer 2 aggregation + log_softmax (R8) ----------------
__global__ __launch_bounds__(256) void agg2_k(const float* __restrict__ b2,
                                              float* __restrict__ out, int n) {
    int w = (blockIdx.x * blockDim.x + threadIdx.x) >> 5;
    if (w >= n) return;
    int l = threadIdx.x & 31;
    float alDv = g_alD2[w];
    int beg = g_rowstart[w], end = g_rowstart[w + 1];
    float acc0 = 0.f, acc1 = 0.f, ssum = 0.f;
    {
        float e = g_alS2[w] + alDv;
        e = e > 0.f ? e : NEG * e;
        float p = __expf(e);
        if (l == 0) ssum += p;
        acc0 += p * g_h2[w * C2 + l];
        if (l < 8) acc1 += p * g_h2[w * C2 + 32 + l];
    }
    for (int j = beg; j < end; j += 32) {
        int jj = j + l;
        bool valid = jj < end;
        int srcv = g_eidx[valid ? jj : j];
        float e = g_alS2[srcv] + alDv;
        e = e > 0.f ? e : NEG * e;
        float q = valid ? __expf(e) : 0.f;
        ssum += q;
        int m = min(32, end - j);
        for (int e2 = 0; e2 < m; e2++) {
            float pp = __shfl_sync(0xFFFFFFFFu, q, e2);
            int sv = __shfl_sync(0xFFFFFFFFu, srcv, e2);
            acc0 += pp * g_h2[sv * C2 + l];
            if (l < 8) acc1 += pp * g_h2[sv * C2 + 32 + l];
        }
    }
#pragma unroll
    for (int o = 16; o; o >>= 1) ssum += __shfl_xor_sync(0xFFFFFFFFu, ssum, o);
    float inv = 1.f / ssum;
    float v0 = acc0 * inv + b2[l];
    float v1 = (l < 8) ? (acc1 * inv + b2[32 + l]) : -3.0e38f;
    float m = fmaxf(v0, v1);
#pragma unroll
    for (int o = 16; o; o >>= 1) m = fmaxf(m, __shfl_xor_sync(0xFFFFFFFFu, m, o));
    float se = __expf(v0 - m) + ((l < 8) ? __expf(v1 - m) : 0.f);
#pragma unroll
    for (int o = 16; o; o >>= 1) se += __shfl_xor_sync(0xFFFFFFFFu, se, o);
    float lse = logf(se) + m;
    out[w * C2 + l] = v0 - lse;
    if (l < 8) out[w * C2 + 32 + l] = v1 - lse;
}

// ---------------- launcher ----------------
extern "C" void kernel_launch(void* const* d_in, const int* in_sizes, int n_in,
                              void* d_out, int out_size) {
    const float* x    = (const float*)d_in[0];
    const float* topo = (const float*)d_in[1];
    const int*   ei   = (const int*)d_in[2];
    const float* W1   = (const float*)d_in[3];
    const float* a_s1 = (const float*)d_in[4];
    const float* a_d1 = (const float*)d_in[5];
    const float* b1   = (const float*)d_in[6];
    const float* W2   = (const float*)d_in[7];
    const float* a_s2 = (const float*)d_in[8];
    const float* a_d2 = (const float*)d_in[9];
    const float* b2   = (const float*)d_in[10];
    float* out = (float*)d_out;

    int n = in_sizes[0] / 120;
    int E = in_sizes[2] / 2;
    int nb = (n + 1023) >> 10;
    int G  = (n + 63) / 64;
    int GA = (G + 1) / 2;
    int GB = G - GA;

    const int GEMM1_SMEM = (8192 + 2 * 64 * SXCH + 1024) * 4;   // 55296 B
    cudaFuncSetAttribute(g1aux_k, cudaFuncAttributeMaxDynamicSharedMemorySize, GEMM1_SMEM);

    // 1: gemm1 first half || count  (independent work, one launch)
    g1aux_k<<<GA + AUXB, 256, GEMM1_SMEM>>>(x, topo, W1, a_s1, a_d1, ei, n, E, GA, 0, 0);
    // 2-3: prefix scans (need count complete)
    scanA_k<<<nb, 1024>>>(n);
    scanC_k<<<(n + 255) / 256, 256>>>(n, E, nb);
    // 4: gemm1 second half || scatter (scatter needs scanC; gemm1 independent)
    g1aux_k<<<GB + AUXB, 256, GEMM1_SMEM>>>(x, topo, W1, a_s1, a_d1, ei, n, E, GB, GA, 1);
    // 5-7: aggregation chain
    agg1_k<<<(n * 32 + 255) / 256, 256>>>(b1, n);
    gemm2_k<<<(n + 63) / 64, 160>>>(W2, a_s2, a_d2, n);
    agg2_k<<<(n * 32 + 255) / 256, 256>>>(b2, out, n);
}